// round 7
// baseline (speedup 1.0000x reference)
#include <cuda_runtime.h>
#include <cuda_bf16.h>
#include <cstdint>

#define NNODE 50000
#define HDIM  128
#define GNUM  64
#define EPSBN 1e-5f

// ---------------- device scratch (no allocs allowed) ----------------
__device__ float g_K [NNODE * HDIM];
__device__ float g_Q [NNODE * HDIM];
__device__ float g_V [NNODE * HDIM];
__device__ float g_H0[NNODE * HDIM];
__device__ float g_H1[NNODE * HDIM];
__device__ float g_pool[GNUM * 2 * HDIM];
__device__ float g_h1m[GNUM * HDIM];
__device__ float g_h2m[GNUM * (HDIM / 2)];
// pre-split operands (bf16x2-packed hi/lo, 64 kpairs per row)
__device__ uint32_t g_XH[NNODE * 64];
__device__ uint32_t g_XL[NNODE * 64];
__device__ uint32_t g_WH[8 * 128 * 64];
__device__ uint32_t g_WL[8 * 128 * 64];

// ---------------- bf16 split helpers ----------------
__device__ __forceinline__ void split2(float x, float y, uint32_t& hi, uint32_t& lo) {
    __nv_bfloat162 h = __floats2bfloat162_rn(x, y);
    float hx = __bfloat162float(h.x);
    float hy = __bfloat162float(h.y);
    __nv_bfloat162 l = __floats2bfloat162_rn(x - hx, y - hy);
    hi = *(uint32_t*)&h;
    lo = *(uint32_t*)&l;
}

__device__ __forceinline__ void mma_bf16(float c[4], const uint32_t a[4], const uint32_t b[2]) {
    asm volatile(
        "mma.sync.aligned.m16n8k16.row.col.f32.bf16.bf16.f32 "
        "{%0,%1,%2,%3}, {%4,%5,%6,%7}, {%8,%9}, {%0,%1,%2,%3};"
        : "+f"(c[0]), "+f"(c[1]), "+f"(c[2]), "+f"(c[3])
        : "r"(a[0]), "r"(a[1]), "r"(a[2]), "r"(a[3]), "r"(b[0]), "r"(b[1]));
}

__device__ __forceinline__ void cp_async16(uint32_t smem_addr, const void* gptr, uint32_t bytes) {
    asm volatile("cp.async.ca.shared.global [%0], [%1], 16, %2;"
                 :: "r"(smem_addr), "l"(gptr), "r"(bytes));
}

// ---------------- prep: split fp32 rows into hi/lo bf16x2 ------------------
template <bool RELU>
__global__ void split_rows_kernel(const float* __restrict__ X, int total_kp,
                                  uint32_t* __restrict__ XH, uint32_t* __restrict__ XL)
{
    const int idx = blockIdx.x * blockDim.x + threadIdx.x;   // kpair id
    if (idx >= total_kp) return;
    const int row = idx >> 6;
    const int k   = idx & 63;
    float2 v = *(const float2*)(X + (long)row * HDIM + 2 * k);
    if (RELU) { v.x = fmaxf(v.x, 0.f); v.y = fmaxf(v.y, 0.f); }
    uint32_t h, l;
    split2(v.x, v.y, h, l);
    XH[idx] = h;
    XL[idx] = l;
}

// grid (32, 8): split 8 weight matrices [128][128] into slots 0..7
__global__ void split_w_kernel(
    const float* __restrict__ w0, const float* __restrict__ w1,
    const float* __restrict__ w2, const float* __restrict__ w3,
    const float* __restrict__ w4, const float* __restrict__ w5,
    const float* __restrict__ w6, const float* __restrict__ w7,
    uint32_t* __restrict__ WH, uint32_t* __restrict__ WL)
{
    const int sel = blockIdx.y;
    const float* w = (sel == 0) ? w0 : (sel == 1) ? w1 : (sel == 2) ? w2 : (sel == 3) ? w3
                   : (sel == 4) ? w4 : (sel == 5) ? w5 : (sel == 6) ? w6 : w7;
    const int idx = blockIdx.x * blockDim.x + threadIdx.x;   // 0..8191
    const int r = idx >> 6;
    const int k = idx & 63;
    float2 v = *(const float2*)(w + (long)r * HDIM + 2 * k);
    uint32_t h, l;
    split2(v.x, v.y, h, l);
    WH[(long)sel * 8192 + idx] = h;
    WL[(long)sel * 8192 + idx] = l;
}

// ---------------- pipelined bf16x3 GEMM on pre-split operands --------------
// grid = (ceil(N/128), 4 weight-select), 512 threads (16 warps, 4x4 warp grid).
// BM=128, BN=128, BK=32 (16 kpairs/stage), cp.async double-buffered.
// smem stage layout: [stage][array(AH,AL,BH,BL)][row 128][kp 16 + pad 4]
#define SKP 20
__global__ __launch_bounds__(512) void gemm_pre_kernel(
    const uint32_t* __restrict__ XH, const uint32_t* __restrict__ XL,
    const uint32_t* __restrict__ WH, const uint32_t* __restrict__ WL,
    const float* __restrict__ bk, const float* __restrict__ bq,
    const float* __restrict__ bv, const float* __restrict__ bs,
    float* __restrict__ oK, float* __restrict__ oQ,
    float* __restrict__ oV, float* __restrict__ oS, int N, int wbase)
{
    const int sel = blockIdx.y;
    const float* bias = (sel == 0) ? bk : (sel == 1) ? bq : (sel == 2) ? bv : bs;
    float*       out  = (sel == 0) ? oK : (sel == 1) ? oQ : (sel == 2) ? oV : oS;
    const uint32_t* wh = WH + (long)(wbase + sel) * 8192;
    const uint32_t* wl = WL + (long)(wbase + sel) * 8192;
    const int m0 = blockIdx.x * 128;

    extern __shared__ uint32_t smem[];   // 2 * 4 * 128 * SKP u32 = 80 KB

    const int tid  = threadIdx.x;
    const int wid  = tid >> 5;
    const int lane = tid & 31;
    const int wm  = wid & 3;        // 0..3 -> 32-row slab
    const int wn  = wid >> 2;       // 0..3 -> 32-col slab
    const int tp  = lane >> 2;      // 0..7
    const int tig = lane & 3;       // 0..3

    float c[2][4][4];
#pragma unroll
    for (int mt = 0; mt < 2; mt++)
#pragma unroll
        for (int nt = 0; nt < 4; nt++)
#pragma unroll
            for (int j = 0; j < 4; j++) c[mt][nt][j] = 0.f;

    // loader mapping: each thread copies one 16B chunk per array per stage
    const int lrow = tid >> 2;        // 0..127
    const int lch  = (tid & 3) * 4;   // kpair offset 0,4,8,12
    const int gmrow = m0 + lrow;
    const bool avalid = gmrow < N;
    const uint32_t abytes = avalid ? 16u : 0u;
    const long aoff = (long)(avalid ? gmrow : 0) * 64 + lch;
    const int  woff = lrow * 64 + lch;
    const int  soff = lrow * SKP + lch;

    auto stage_base = [&](int st, int arr) -> uint32_t* {
        return smem + ((st * 4 + arr) * 128 * SKP);
    };
    auto load_stage = [&](int st, int kp0) {
        cp_async16((uint32_t)__cvta_generic_to_shared(stage_base(st, 0) + soff), XH + aoff + kp0, abytes);
        cp_async16((uint32_t)__cvta_generic_to_shared(stage_base(st, 1) + soff), XL + aoff + kp0, abytes);
        cp_async16((uint32_t)__cvta_generic_to_shared(stage_base(st, 2) + soff), wh + woff + kp0, 16u);
        cp_async16((uint32_t)__cvta_generic_to_shared(stage_base(st, 3) + soff), wl + woff + kp0, 16u);
        asm volatile("cp.async.commit_group;" ::: "memory");
    };

    load_stage(0, 0);
    load_stage(1, 16);

#pragma unroll
    for (int t = 0; t < 4; t++) {
        if (t < 3) asm volatile("cp.async.wait_group 1;" ::: "memory");
        else       asm volatile("cp.async.wait_group 0;" ::: "memory");
        __syncthreads();

        const uint32_t* AH = stage_base(t & 1, 0);
        const uint32_t* AL = stage_base(t & 1, 1);
        const uint32_t* BH = stage_base(t & 1, 2);
        const uint32_t* BL = stage_base(t & 1, 3);

#pragma unroll
        for (int ks = 0; ks < 2; ks++) {
            const int kb = ks * 8;
            uint32_t ah[2][4], al[2][4];
#pragma unroll
            for (int mt = 0; mt < 2; mt++) {
                const int r = wm * 32 + mt * 16 + tp;
                ah[mt][0] = AH[r * SKP + kb + tig];
                ah[mt][1] = AH[(r + 8) * SKP + kb + tig];
                ah[mt][2] = AH[r * SKP + kb + tig + 4];
                ah[mt][3] = AH[(r + 8) * SKP + kb + tig + 4];
                al[mt][0] = AL[r * SKP + kb + tig];
                al[mt][1] = AL[(r + 8) * SKP + kb + tig];
                al[mt][2] = AL[r * SKP + kb + tig + 4];
                al[mt][3] = AL[(r + 8) * SKP + kb + tig + 4];
            }
            uint32_t bh[4][2], bl[4][2];
#pragma unroll
            for (int nt = 0; nt < 4; nt++) {
                const int col = wn * 32 + nt * 8 + tp;
                bh[nt][0] = BH[col * SKP + kb + tig];
                bh[nt][1] = BH[col * SKP + kb + tig + 4];
                bl[nt][0] = BL[col * SKP + kb + tig];
                bl[nt][1] = BL[col * SKP + kb + tig + 4];
            }
#pragma unroll
            for (int mt = 0; mt < 2; mt++)
#pragma unroll
                for (int nt = 0; nt < 4; nt++) {
                    mma_bf16(c[mt][nt], ah[mt], bl[nt]);   // cross terms
                    mma_bf16(c[mt][nt], al[mt], bh[nt]);
                    mma_bf16(c[mt][nt], ah[mt], bh[nt]);   // main term
                }
        }
        __syncthreads();
        if (t < 2) load_stage(t & 1, (t + 2) * 16);
    }

    // epilogue: bias add + store
#pragma unroll
    for (int nt = 0; nt < 4; nt++) {
        const int col = wn * 32 + nt * 8 + 2 * tig;
        const float b0 = bias[col];
        const float b1 = bias[col + 1];
#pragma unroll
        for (int mt = 0; mt < 2; mt++) {
            const int r0 = m0 + wm * 32 + mt * 16 + tp;
            const int r1 = r0 + 8;
            if (r0 < N) {
                float2 v = make_float2(c[mt][nt][0] + b0, c[mt][nt][1] + b1);
                *(float2*)(out + (long)r0 * HDIM + col) = v;
            }
            if (r1 < N) {
                float2 v = make_float2(c[mt][nt][2] + b0, c[mt][nt][3] + b1);
                *(float2*)(out + (long)r1 * HDIM + col) = v;
            }
        }
    }
}

// ---------------- edge kernel: 2 edges per warp, phase-split (proven) ------
__global__ __launch_bounds__(256) void edge_kernel(
    const int* __restrict__ ei, int E,
    const float* __restrict__ K, const float* __restrict__ Q,
    const float* __restrict__ V, float* __restrict__ AGG)
{
    const int w    = (blockIdx.x * blockDim.x + threadIdx.x) >> 5;
    const int lane = threadIdx.x & 31;
    const int e0   = w * 2;
    if (e0 >= E) return;
    const int e1   = (e0 + 1 < E) ? e0 + 1 : e0;

    const int s0 = __ldg(ei + e0);
    const int s1 = __ldg(ei + e1);
    const int d0 = __ldg(ei + E + e0);
    const int d1 = __ldg(ei + E + e1);

    const float4 k0 = *(const float4*)(K + (long)d0 * HDIM + lane * 4);
    const float4 q0 = *(const float4*)(Q + (long)s0 * HDIM + lane * 4);
    const float4 v0 = *(const float4*)(V + (long)s0 * HDIM + lane * 4);
    const float4 k1 = *(const float4*)(K + (long)d1 * HDIM + lane * 4);
    const float4 q1 = *(const float4*)(Q + (long)s1 * HDIM + lane * 4);
    const float4 v1 = *(const float4*)(V + (long)s1 * HDIM + lane * 4);

    {
        const float g0 = 1.f / (1.f + __expf(-(k0.x + q0.x)));
        const float g1 = 1.f / (1.f + __expf(-(k0.y + q0.y)));
        const float g2 = 1.f / (1.f + __expf(-(k0.z + q0.z)));
        const float g3 = 1.f / (1.f + __expf(-(k0.w + q0.w)));
        float* o = AGG + (long)d0 * HDIM + lane * 4;
        asm volatile("red.global.add.v4.f32 [%0], {%1, %2, %3, %4};"
                     :: "l"(o), "f"(g0 * v0.x), "f"(g1 * v0.y),
                        "f"(g2 * v0.z), "f"(g3 * v0.w)
                     : "memory");
    }
    if (e0 + 1 < E) {
        const float g0 = 1.f / (1.f + __expf(-(k1.x + q1.x)));
        const float g1 = 1.f / (1.f + __expf(-(k1.y + q1.y)));
        const float g2 = 1.f / (1.f + __expf(-(k1.z + q1.z)));
        const float g3 = 1.f / (1.f + __expf(-(k1.w + q1.w)));
        float* o = AGG + (long)d1 * HDIM + lane * 4;
        asm volatile("red.global.add.v4.f32 [%0], {%1, %2, %3, %4};"
                     :: "l"(o), "f"(g0 * v1.x), "f"(g1 * v1.y),
                        "f"(g2 * v1.z), "f"(g3 * v1.w)
                     : "memory");
    }
}

// ---------------- pooling (proven) -----------------------------------------
__device__ __forceinline__ int lower_bound_i(const int* a, int n, int v) {
    int lo = 0, hi = n;
    while (lo < hi) { int m = (lo + hi) >> 1; if (a[m] < v) lo = m + 1; else hi = m; }
    return lo;
}

__global__ void pool_kernel(const float* __restrict__ H,
                            const int* __restrict__ batch, int N,
                            float* __restrict__ pool)
{
    const int g    = blockIdx.x;
    const int c    = blockIdx.y * 32 + (threadIdx.x & 31);
    const int rloc = threadIdx.x >> 5;          // 0..3
    const int lo = lower_bound_i(batch, N, g);
    const int hi = lower_bound_i(batch, N, g + 1);
    float mx = -3.402823466e38f;
    float sm = 0.f;
    for (int n = lo + rloc; n < hi; n += 4) {
        const float x = H[(long)n * HDIM + c];
        mx = fmaxf(mx, x);
        sm += x;
    }
    __shared__ float smx[4][32], ssm[4][32];
    smx[rloc][threadIdx.x & 31] = mx;
    ssm[rloc][threadIdx.x & 31] = sm;
    __syncthreads();
    if (rloc == 0) {
        const int l = threadIdx.x & 31;
        mx = fmaxf(fmaxf(smx[0][l], smx[1][l]), fmaxf(smx[2][l], smx[3][l]));
        sm = ssm[0][l] + ssm[1][l] + ssm[2][l] + ssm[3][l];
        const int cnt = hi - lo;
        pool[g * (2 * HDIM) + c]        = (cnt > 0) ? mx : 0.f;
        pool[g * (2 * HDIM) + HDIM + c] = sm / fmaxf((float)cnt, 1.f);
    }
}

// ---------------- MLP head (proven) ----------------------------------------
__global__ void mlp1_kernel(const float* __restrict__ pool,
                            const float* __restrict__ W1, const float* __restrict__ b1,
                            const float* __restrict__ g1, const float* __restrict__ be1,
                            float* __restrict__ h1)
{
    const int c = blockIdx.x;   // 0..127
    const int r = threadIdx.x;  // 0..63
    float acc = b1[c];
    const float* w = W1 + (long)c * (2 * HDIM);
    const float* f = pool + (long)r * (2 * HDIM);
#pragma unroll 8
    for (int i = 0; i < 2 * HDIM; i++) acc += f[i] * w[i];

    __shared__ float red[GNUM];
    red[r] = acc; __syncthreads();
    float m = 0.f;
    if (r == 0) { for (int i = 0; i < GNUM; i++) m += red[i]; red[0] = m / GNUM; }
    __syncthreads();
    m = red[0]; __syncthreads();
    red[r] = (acc - m) * (acc - m); __syncthreads();
    float v = 0.f;
    if (r == 0) { for (int i = 0; i < GNUM; i++) v += red[i]; red[0] = v / GNUM; }
    __syncthreads();
    v = red[0];
    const float y = g1[c] * (acc - m) * rsqrtf(v + EPSBN) + be1[c];
    h1[(long)r * HDIM + c] = fmaxf(y, 0.f);
}

__global__ void mlp2_kernel(const float* __restrict__ h1,
                            const float* __restrict__ W2, const float* __restrict__ b2,
                            const float* __restrict__ g2, const float* __restrict__ be2,
                            float* __restrict__ h2)
{
    const int c = blockIdx.x;   // 0..63
    const int r = threadIdx.x;  // 0..63
    float acc = b2[c];
    const float* w = W2 + (long)c * HDIM;
    const float* f = h1 + (long)r * HDIM;
#pragma unroll 8
    for (int i = 0; i < HDIM; i++) acc += f[i] * w[i];

    __shared__ float red[GNUM];
    red[r] = acc; __syncthreads();
    float m = 0.f;
    if (r == 0) { for (int i = 0; i < GNUM; i++) m += red[i]; red[0] = m / GNUM; }
    __syncthreads();
    m = red[0]; __syncthreads();
    red[r] = (acc - m) * (acc - m); __syncthreads();
    float v = 0.f;
    if (r == 0) { for (int i = 0; i < GNUM; i++) v += red[i]; red[0] = v / GNUM; }
    __syncthreads();
    v = red[0];
    const float y = g2[c] * (acc - m) * rsqrtf(v + EPSBN) + be2[c];
    h2[(long)r * (HDIM / 2) + c] = fmaxf(y, 0.f);
}

__global__ void mlp3_kernel(const float* __restrict__ h2,
                            const float* __restrict__ W3, const float* __restrict__ b3,
                            float* __restrict__ out)
{
    const int r = threadIdx.x;
    float acc = b3[0];
#pragma unroll
    for (int i = 0; i < HDIM / 2; i++) acc += h2[(long)r * (HDIM / 2) + i] * W3[i];
    out[r] = acc;
}

// ---------------- launch -----------------
extern "C" void kernel_launch(void* const* d_in, const int* in_sizes, int n_in,
                              void* d_out, int out_size)
{
    const float* x     = (const float*)d_in[0];
    const int*   ei    = (const int*)d_in[1];
    const int*   batch = (const int*)d_in[2];
    const int N = in_sizes[0] / HDIM;
    const int E = in_sizes[1] / 2;

    const float* l0W[4], *l0b[4], *l1W[4], *l1b[4];
    for (int i = 0; i < 4; i++) {
        l0W[i] = (const float*)d_in[3 + 2 * i];
        l0b[i] = (const float*)d_in[4 + 2 * i];
        l1W[i] = (const float*)d_in[11 + 2 * i];
        l1b[i] = (const float*)d_in[12 + 2 * i];
    }
    const float* W1  = (const float*)d_in[19];
    const float* b1  = (const float*)d_in[20];
    const float* g1  = (const float*)d_in[21];
    const float* be1 = (const float*)d_in[22];
    const float* W2  = (const float*)d_in[23];
    const float* b2  = (const float*)d_in[24];
    const float* g2  = (const float*)d_in[25];
    const float* be2 = (const float*)d_in[26];
    const float* W3  = (const float*)d_in[27];
    const float* b3  = (const float*)d_in[28];
    float* out = (float*)d_out;

    float *pK, *pQ, *pV, *pH0, *pH1, *pPool, *pM1, *pM2;
    uint32_t *pXH, *pXL, *pWH, *pWL;
    cudaGetSymbolAddress((void**)&pK,  g_K);
    cudaGetSymbolAddress((void**)&pQ,  g_Q);
    cudaGetSymbolAddress((void**)&pV,  g_V);
    cudaGetSymbolAddress((void**)&pH0, g_H0);
    cudaGetSymbolAddress((void**)&pH1, g_H1);
    cudaGetSymbolAddress((void**)&pPool, g_pool);
    cudaGetSymbolAddress((void**)&pM1, g_h1m);
    cudaGetSymbolAddress((void**)&pM2, g_h2m);
    cudaGetSymbolAddress((void**)&pXH, g_XH);
    cudaGetSymbolAddress((void**)&pXL, g_XL);
    cudaGetSymbolAddress((void**)&pWH, g_WH);
    cudaGetSymbolAddress((void**)&pWL, g_WL);

    static bool smem_set = false;
    (void)smem_set;
    cudaFuncSetAttribute(gemm_pre_kernel,
                         cudaFuncAttributeMaxDynamicSharedMemorySize, 2 * 4 * 128 * SKP * 4);

    const dim3 ggrid((N + 127) / 128, 4);
    const int  gsmem  = 2 * 4 * 128 * SKP * 4;   // 81920 B
    const int eblocks = (E + 15) / 16;   // 8 warps/block, 2 edges per warp
    const int total_kp = N * 64;
    const int sblocks = (total_kp + 255) / 256;

    // prep: split weights (all 8) and X
    split_w_kernel<<<dim3(32, 8), 256>>>(
        l0W[0], l0W[1], l0W[2], l0W[3], l1W[0], l1W[1], l1W[2], l1W[3], pWH, pWL);
    split_rows_kernel<false><<<sblocks, 256>>>(x, total_kp, pXH, pXL);

    // layer 0
    gemm_pre_kernel<<<ggrid, 512, gsmem>>>(pXH, pXL, pWH, pWL,
        l0b[0], l0b[1], l0b[2], l0b[3], pK, pQ, pV, pH0, N, 0);
    edge_kernel<<<eblocks, 256>>>(ei, E, pK, pQ, pV, pH0);

    // layer 1: relu + split H0, then GEMM on slots 4..7
    split_rows_kernel<true><<<sblocks, 256>>>(pH0, total_kp, pXH, pXL);
    gemm_pre_kernel<<<ggrid, 512, gsmem>>>(pXH, pXL, pWH, pWL,
        l1b[0], l1b[1], l1b[2], l1b[3], pK, pQ, pV, pH1, N, 4);
    edge_kernel<<<eblocks, 256>>>(ei, E, pK, pQ, pV, pH1);

    // pooling + head (proven)
    pool_kernel<<<dim3(GNUM, 4), 128>>>(pH1, batch, N, pPool);
    mlp1_kernel<<<HDIM, GNUM>>>(pPool, W1, b1, g1, be1, pM1);
    mlp2_kernel<<<HDIM / 2, GNUM>>>(pM1, W2, b2, g2, be2, pM2);
    mlp3_kernel<<<1, GNUM>>>(pM2, W3, b3, out);
}